// round 2
// baseline (speedup 1.0000x reference)
#include <cuda_runtime.h>
#include <cuda_bf16.h>
#include <math.h>

#define B_   32
#define T_   2048
#define D_   1024
#define MEM_ 64
#define HID_ 512   // D/2

// ---------------- device scratch (no allocations allowed) ----------------
// __align__(16) is required: these are accessed through float4* casts, and
// __device__ float[] only guarantees 4-byte natural alignment.
__device__ __align__(16) float g_part[16 * B_ * D_];   // mean partials [ts][b][d]
__device__ __align__(16) float g_xm  [B_ * D_];        // time-mean     [b][d]
__device__ __align__(16) float g_pxp [8 * B_ * D_];    // xp partials   [ks][b][e]
__device__ __align__(16) float g_xp  [B_ * D_];        // projected     [b][e]
__device__ __align__(16) float g_ph  [16 * B_ * HID_]; // h partials    [ks][b][j]
__device__ __align__(16) float g_h   [B_ * HID_];      // silu hidden   [b][j]
__device__ float g_gate[B_];
__device__ int   g_best[B_];

// ---------------- K1: mean over T, partial sums ----------------
// grid (16 tsplits, 32 batches), 256 threads; each thread owns 4 d-columns (float4)
__global__ __launch_bounds__(256) void k1_mean_partial(const float* __restrict__ x) {
    int ts = blockIdx.x;   // 0..15
    int b  = blockIdx.y;   // 0..31
    int tid = threadIdx.x;
    const float4* p = (const float4*)(x + ((size_t)b * T_ + (size_t)ts * 128) * D_) + tid;
    float4 a0 = {0,0,0,0}, a1 = a0, a2 = a0, a3 = a0;
    #pragma unroll 2
    for (int t = 0; t < 128; t += 4) {
        float4 v0 = p[(t + 0) * (D_/4)];
        float4 v1 = p[(t + 1) * (D_/4)];
        float4 v2 = p[(t + 2) * (D_/4)];
        float4 v3 = p[(t + 3) * (D_/4)];
        a0.x += v0.x; a0.y += v0.y; a0.z += v0.z; a0.w += v0.w;
        a1.x += v1.x; a1.y += v1.y; a1.z += v1.z; a1.w += v1.w;
        a2.x += v2.x; a2.y += v2.y; a2.z += v2.z; a2.w += v2.w;
        a3.x += v3.x; a3.y += v3.y; a3.z += v3.z; a3.w += v3.w;
    }
    float4 s;
    s.x = (a0.x + a1.x) + (a2.x + a3.x);
    s.y = (a0.y + a1.y) + (a2.y + a3.y);
    s.z = (a0.z + a1.z) + (a2.z + a3.z);
    s.w = (a0.w + a1.w) + (a2.w + a3.w);
    ((float4*)g_part)[(ts * B_ + b) * (D_/4) + tid] = s;
}

// ---------------- K2: finalize mean ----------------
__global__ __launch_bounds__(256) void k2_finalize_mean() {
    int i = blockIdx.x * 256 + threadIdx.x;   // 32768 = b*1024+d
    float s = 0.f;
    #pragma unroll
    for (int ts = 0; ts < 16; ts++) s += g_part[ts * (B_ * D_) + i];
    g_xm[i] = s * (1.0f / (float)T_);
}

// ---------------- K3: xp split-K GEMM  xp[b,e] = sum_d xm[b,d]*W[e,d] ----------------
// grid (16 e-tiles of 64, 8 k-splits of 128), 256 threads, thread tile 2b x 4e
__global__ __launch_bounds__(256) void k3_gemm_xp(const float* __restrict__ W) {
    __shared__ float As[B_][129];   // [b][k]  (pad -> conflict-free)
    __shared__ float Ws[64][129];   // [e][k]
    int et = blockIdx.x, ks = blockIdx.y;
    int e0 = et * 64, k0 = ks * 128;
    int tid = threadIdx.x;
    {   // load A 32x128
        int b = tid >> 3;
        int kk0 = (tid & 7) * 16;
        const float* src = g_xm + b * D_ + k0 + kk0;
        #pragma unroll
        for (int j = 0; j < 16; j++) As[b][kk0 + j] = src[j];
    }
    {   // load W 64x128
        int e = tid >> 2;
        int kk0 = (tid & 3) * 32;
        const float* src = W + (size_t)(e0 + e) * D_ + k0 + kk0;
        #pragma unroll
        for (int j = 0; j < 32; j++) Ws[e][kk0 + j] = src[j];
    }
    __syncthreads();
    int tb = tid & 15, te = tid >> 4;
    float accA[4] = {0,0,0,0}, accB[4] = {0,0,0,0};
    #pragma unroll 4
    for (int k = 0; k < 128; k++) {
        float a0 = As[tb][k], a1 = As[tb + 16][k];
        #pragma unroll
        for (int i = 0; i < 4; i++) {
            float w = Ws[te * 4 + i][k];
            accA[i] += a0 * w;
            accB[i] += a1 * w;
        }
    }
    #pragma unroll
    for (int i = 0; i < 4; i++) {
        g_pxp[(ks * B_ + tb     ) * D_ + e0 + te * 4 + i] = accA[i];
        g_pxp[(ks * B_ + tb + 16) * D_ + e0 + te * 4 + i] = accB[i];
    }
}

// ---------------- K4: reduce xp partials + bias ----------------
__global__ __launch_bounds__(256) void k4_reduce_xp(const float* __restrict__ bias) {
    int i = blockIdx.x * 256 + threadIdx.x;   // 32768
    float s = 0.f;
    #pragma unroll
    for (int ks = 0; ks < 8; ks++) s += g_pxp[ks * (B_ * D_) + i];
    g_xp[i] = s + bias[i & (D_ - 1)];
}

// ---------------- K5: MLP split-K GEMM  h[b,j] = sum_d xp[b,d]*W1[j,d] ----------------
// grid (8 e-tiles of 64, 16 k-splits of 64), 256 threads
__global__ __launch_bounds__(256) void k5_gemm_mlp(const float* __restrict__ W1) {
    __shared__ float As[B_][65];
    __shared__ float Ws[64][65];
    int et = blockIdx.x, ks = blockIdx.y;
    int e0 = et * 64, k0 = ks * 64;
    int tid = threadIdx.x;
    {   // load A 32x64
        int b = tid >> 3;
        int kk0 = (tid & 7) * 8;
        const float* src = g_xp + b * D_ + k0 + kk0;
        #pragma unroll
        for (int j = 0; j < 8; j++) As[b][kk0 + j] = src[j];
    }
    {   // load W 64x64
        int e = tid >> 2;
        int kk0 = (tid & 3) * 16;
        const float* src = W1 + (size_t)(e0 + e) * D_ + k0 + kk0;
        #pragma unroll
        for (int j = 0; j < 16; j++) Ws[e][kk0 + j] = src[j];
    }
    __syncthreads();
    int tb = tid & 15, te = tid >> 4;
    float accA[4] = {0,0,0,0}, accB[4] = {0,0,0,0};
    #pragma unroll 4
    for (int k = 0; k < 64; k++) {
        float a0 = As[tb][k], a1 = As[tb + 16][k];
        #pragma unroll
        for (int i = 0; i < 4; i++) {
            float w = Ws[te * 4 + i][k];
            accA[i] += a0 * w;
            accB[i] += a1 * w;
        }
    }
    #pragma unroll
    for (int i = 0; i < 4; i++) {
        g_ph[(ks * B_ + tb     ) * HID_ + e0 + te * 4 + i] = accA[i];
        g_ph[(ks * B_ + tb + 16) * HID_ + e0 + te * 4 + i] = accB[i];
    }
}

// ---------------- K6: reduce h partials + bias + SiLU ----------------
__global__ __launch_bounds__(256) void k6_reduce_h(const float* __restrict__ bias) {
    int i = blockIdx.x * 256 + threadIdx.x;   // 16384
    float s = 0.f;
    #pragma unroll
    for (int ks = 0; ks < 16; ks++) s += g_ph[ks * (B_ * HID_) + i];
    s += bias[i & (HID_ - 1)];
    g_h[i] = s / (1.0f + expf(-s));   // silu
}

// ---------------- block reduce helper ----------------
__device__ __forceinline__ float blockReduce(float v, volatile float* rbuf) {
    unsigned m = 0xffffffffu;
    v += __shfl_down_sync(m, v, 16);
    v += __shfl_down_sync(m, v, 8);
    v += __shfl_down_sync(m, v, 4);
    v += __shfl_down_sync(m, v, 2);
    v += __shfl_down_sync(m, v, 1);
    __syncthreads();                              // protect rbuf reuse
    if ((threadIdx.x & 31) == 0) rbuf[threadIdx.x >> 5] = v;
    __syncthreads();
    float s = rbuf[0];
    #pragma unroll
    for (int i = 1; i < 8; i++) s += rbuf[i];
    return s;
}

// ---------------- K7: per-batch tail ----------------
// grid 32 blocks x 256 threads
__global__ __launch_bounds__(256) void k7_tail(
    const float* __restrict__ mkey0, const float* __restrict__ mkey1,
    const float* __restrict__ keym,  const float* __restrict__ valm,
    const float* __restrict__ w2,    const float* __restrict__ b2,
    const float* __restrict__ cw,    const float* __restrict__ cb) {
    int b = blockIdx.x;
    int tid = threadIdx.x;
    int lane = tid & 31;
    __shared__ float xps[D_];
    __shared__ float rbuf[8];
    __shared__ float logits[MEM_];

    const float* xp = g_xp + b * D_;
    float4 v  = ((const float4*)xp)[tid];
    ((float4*)xps)[tid] = v;
    float4 m0 = ((const float4*)mkey0)[tid];
    float4 m1 = ((const float4*)mkey1)[tid];

    float xsq = v.x*v.x + v.y*v.y + v.z*v.z + v.w*v.w;
    float d0  = v.x*m0.x + v.y*m0.y + v.z*m0.z + v.w*m0.w;
    float d1  = v.x*m1.x + v.y*m1.y + v.z*m1.z + v.w*m1.w;
    float n0  = m0.x*m0.x + m0.y*m0.y + m0.z*m0.z + m0.w*m0.w;
    float n1  = m1.x*m1.x + m1.y*m1.y + m1.z*m1.z + m1.w*m1.w;

    xsq = blockReduce(xsq, rbuf);
    d0  = blockReduce(d0,  rbuf);
    d1  = blockReduce(d1,  rbuf);
    n0  = blockReduce(n0,  rbuf);
    n1  = blockReduce(n1,  rbuf);
    // xps is now visible to all threads (syncthreads inside reduces)

    float nx = sqrtf(xsq);
    float s0 = d0 / fmaxf(nx * sqrtf(n0), 1e-8f);
    float s1 = d1 / fmaxf(nx * sqrtf(n1), 1e-8f);
    int best = (s1 > s0) ? 1 : 0;   // argmax, first index on tie

    // attention logits: warp w handles keys w*8 .. w*8+7
    float inv_nx = 1.0f / fmaxf(nx, 1e-12f);
    int w = tid >> 5;
    #pragma unroll
    for (int q = 0; q < 8; q++) {
        int mrow = w * 8 + q;
        const float* kr = keym + mrow * D_;
        float dot = 0.f, ksq = 0.f;
        #pragma unroll 4
        for (int j = lane; j < D_; j += 32) {
            float kv = kr[j];
            dot += kv * xps[j];
            ksq += kv * kv;
        }
        #pragma unroll
        for (int o = 16; o > 0; o >>= 1) {
            dot += __shfl_down_sync(0xffffffffu, dot, o);
            ksq += __shfl_down_sync(0xffffffffu, ksq, o);
        }
        if (lane == 0) {
            float nk = sqrtf(ksq);
            logits[mrow] = dot * inv_nx / fmaxf(nk, 1e-12f) * (1.0f / 32.0f); // /sqrt(1024)
        }
    }

    // mlp_out = dot(h[b], w2) + b2  (reduce also acts as barrier before softmax reads logits)
    const float* hb = g_h + b * HID_;
    float mp = hb[tid * 2] * w2[tid * 2] + hb[tid * 2 + 1] * w2[tid * 2 + 1];
    float mlp_out = blockReduce(mp, rbuf) + b2[0];

    // warp 0: softmax over 64 logits, dot with valm
    if (tid < 32) {
        float l0 = logits[tid], l1 = logits[tid + 32];
        float mx = fmaxf(l0, l1);
        #pragma unroll
        for (int o = 16; o > 0; o >>= 1) mx = fmaxf(mx, __shfl_xor_sync(0xffffffffu, mx, o));
        float e0 = expf(l0 - mx), e1 = expf(l1 - mx);
        float ssum = e0 + e1;
        float vsum = e0 * valm[tid] + e1 * valm[tid + 32];
        #pragma unroll
        for (int o = 16; o > 0; o >>= 1) {
            ssum += __shfl_down_sync(0xffffffffu, ssum, o);
            vsum += __shfl_down_sync(0xffffffffu, vsum, o);
        }
        if (tid == 0) {
            float mem_val = vsum / ssum;
            g_gate[b] = cw[0] * mem_val + cw[1] * mlp_out + cb[0];
            g_best[b] = best;
        }
    }
}

// ---------------- K8: change detector + outputs ----------------
// out[0..31] = scalar, out[32..63] = gate
__global__ void k8_final(float* __restrict__ out, const float* __restrict__ thr) {
    int b = threadIdx.x;   // 32 threads
    float t = thr[0];
    int bb = g_best[b];
    float changed = (b == 0) ? 1.0f : ((bb != g_best[b - 1]) ? 1.0f : 0.0f);
    out[b]       = (changed > t) ? 1.0f : 0.0f;
    out[B_ + b]  = g_gate[b];
}

// ---------------- launch ----------------
extern "C" void kernel_launch(void* const* d_in, const int* in_sizes, int n_in,
                              void* d_out, int out_size) {
    const float* x       = (const float*)d_in[0];
    const float* mkey0   = (const float*)d_in[1];
    const float* mkey1   = (const float*)d_in[2];
    const float* keym    = (const float*)d_in[3];
    const float* valm    = (const float*)d_in[4];
    const float* mlp_w1  = (const float*)d_in[5];
    const float* mlp_b1  = (const float*)d_in[6];
    const float* mlp_w2  = (const float*)d_in[7];
    const float* mlp_b2  = (const float*)d_in[8];
    const float* cw      = (const float*)d_in[9];
    const float* cb      = (const float*)d_in[10];
    const float* xa_w    = (const float*)d_in[11];
    const float* xa_b    = (const float*)d_in[12];
    const float* thr     = (const float*)d_in[13];
    float* out = (float*)d_out;

    k1_mean_partial<<<dim3(16, 32), 256>>>(x);
    k2_finalize_mean<<<128, 256>>>();
    k3_gemm_xp<<<dim3(16, 8), 256>>>(xa_w);
    k4_reduce_xp<<<128, 256>>>(xa_b);
    k5_gemm_mlp<<<dim3(8, 16), 256>>>(mlp_w1);
    k6_reduce_h<<<64, 256>>>(mlp_b1);
    k7_tail<<<32, 256>>>(mkey0, mkey1, keym, valm, mlp_w2, mlp_b2, cw, cb);
    k8_final<<<1, 32>>>(out, thr);
}